// round 9
// baseline (speedup 1.0000x reference)
#include <cuda_runtime.h>

// SConv2d majority-gate conv, s-domain math, packed f32x2 (2 px/thread).
// R8: 9-way channel split — one thread = (pixel-pair, 3-channel group).
//     3x thread count (331776) to raise occupancy; carried tree state is
//     only 3 u64 per oc. 4-row tiles, 576-thread blocks, grid 576.

#define C_IN 27
#define NOC 27
#define HH 32
#define WW 32
#define TILE_H 4
#define SM_ROWS (TILE_H + 2)       // 6
#define SM_W 36                    // [pad, haloL, 32 interior, haloR, pad]
#define SM_CH (SM_ROWS * SM_W)     // 216
#define OCG 3
#define WP2 10                     // packed-weight stride per (oc,c) in u64
#define NPAIR 64                   // pixel pairs per tile (4 rows x 16)
#define NCG 9                      // channel groups (3 channels each)
#define NTHR (NPAIR * NCG)         // 576

typedef unsigned long long u64;

__device__ __forceinline__ u64 pk2(float lo, float hi) {
    u64 r; asm("mov.b64 %0,{%1,%2};" : "=l"(r) : "f"(lo), "f"(hi)); return r;
}
__device__ __forceinline__ void upk2(u64 v, float& lo, float& hi) {
    asm("mov.b64 {%0,%1},%2;" : "=f"(lo), "=f"(hi) : "l"(v));
}
__device__ __forceinline__ u64 ffma2(u64 a, u64 b, u64 c) {
    u64 d; asm("fma.rn.f32x2 %0,%1,%2,%3;" : "=l"(d) : "l"(a), "l"(b), "l"(c)); return d;
}
__device__ __forceinline__ u64 fmul2(u64 a, u64 b) {
    u64 d; asm("mul.rn.f32x2 %0,%1,%2;" : "=l"(d) : "l"(a), "l"(b)); return d;
}
__device__ __forceinline__ u64 fadd2(u64 a, u64 b) {
    u64 d; asm("add.rn.f32x2 %0,%1,%2;" : "=l"(d) : "l"(a), "l"(b)); return d;
}
__device__ __forceinline__ u64 maj3s2(u64 a, u64 b, u64 c, u64 NEG2) {
    u64 p = fmul2(a, b);
    u64 t = fadd2(a, b);
    u64 q = ffma2(NEG2, p, t);     // a+b-2ab
    return ffma2(q, c, p);         // ab + (a+b-2ab)c
}

__global__ __launch_bounds__(NTHR, 2) void sconv_kernel(const float* __restrict__ x,
                                                        const float* __restrict__ w,
                                                        float* __restrict__ out) {
    __shared__ __align__(16) float xs[C_IN * SM_CH];        // 23328 B (aliased later)
    __shared__ __align__(16) u64 wsm[OCG * C_IN * WP2];     // 6480 B

    int b = blockIdx.x;
    int ocg  = b % NCG;            // 0..8 -> oc group
    int tile = (b / NCG) & 7;      // 0..7 -> 4-row tile
    int n    = b / (8 * NCG);      // 0..7
    int h0 = tile * TILE_H;
    int oc0 = ocg * OCG;

    int tid = threadIdx.x;

    // ---- stage weights packed {w/2, w/2}
    for (int idx = tid; idx < OCG * C_IN * 9; idx += NTHR) {
        int ocl = idx / (C_IN * 9);
        int rem = idx - ocl * (C_IN * 9);
        int c = rem / 9;
        int k = rem - c * 9;
        float v = 0.5f * w[(oc0 + ocl) * (C_IN * 9) + rem];
        wsm[(ocl * C_IN + c) * WP2 + k] = pk2(v, v);
    }

    // ---- stage x tile interior (coalesced); halos = -1
    const float* xn = x + (size_t)n * C_IN * HH * WW;
    for (int idx = tid; idx < C_IN * SM_ROWS * 32; idx += NTHR) {
        int rowid = idx >> 5;
        int col   = idx & 31;
        int c = rowid / SM_ROWS;
        int r = rowid - c * SM_ROWS;
        int gh = h0 + r - 1;
        float v = -1.0f;
        if ((unsigned)gh < HH)
            v = xn[(c << 10) + (gh << 5) + col];
        xs[c * SM_CH + r * SM_W + col + 2] = v;
    }
    for (int idx = tid; idx < C_IN * SM_ROWS; idx += NTHR) {
        xs[idx * SM_W + 1]  = -1.0f;
        xs[idx * SM_W + 34] = -1.0f;
    }
    __syncthreads();

    int pp = tid & (NPAIR - 1);        // pair index 0..63
    int cg = tid / NPAIR;              // channel group 0..8
    int wc2 = pp & 15;                 // pair column
    int hl  = pp >> 4;                 // local row 0..3

    const u64 HALF2 = pk2(0.5f, 0.5f);
    const u64 NEG2  = pk2(-2.0f, -2.0f);

    const float* xb = &xs[hl * SM_W + 2 + 2 * wc2];
    int c0 = 3 * cg;

    u64 vb[OCG][3];

    #pragma unroll
    for (int cl = 0; cl < 3; cl++) {
        int c = c0 + cl;
        // 9 packed x pairs for this channel
        u64 xp[9];
        #pragma unroll
        for (int kh = 0; kh < 3; kh++) {
            const float* rp = xb + c * SM_CH + kh * SM_W;
            float2 a  = *(const float2*)rp;
            float  bl = rp[-1];
            float2 cr = *(const float2*)(rp + 2);
            xp[kh * 3 + 0] = pk2(bl, a.x);
            xp[kh * 3 + 1] = pk2(a.x, a.y);
            xp[kh * 3 + 2] = pk2(a.y, cr.x);
        }
        #pragma unroll
        for (int o = 0; o < OCG; o++) {
            const u64* wb_ = &wsm[(o * C_IN + c) * WP2];
            u64 rkh[3];
            #pragma unroll
            for (int kh = 0; kh < 3; kh++) {
                // load 3 weights for this row, consume immediately
                u64 w0 = wb_[kh * 3 + 0];
                u64 w1 = wb_[kh * 3 + 1];
                u64 w2 = wb_[kh * 3 + 2];
                u64 s0 = ffma2(xp[kh * 3 + 0], w0, HALF2);
                u64 s1 = ffma2(xp[kh * 3 + 1], w1, HALF2);
                u64 s2 = ffma2(xp[kh * 3 + 2], w2, HALF2);
                rkh[kh] = maj3s2(s0, s1, s2, NEG2);
            }
            vb[o][cl] = maj3s2(rkh[0], rkh[1], rkh[2], NEG2);
        }
    }

    // u-node per oc for this 3-channel group
    u64 up[OCG];
    #pragma unroll
    for (int o = 0; o < OCG; o++)
        up[o] = maj3s2(vb[o][0], vb[o][1], vb[o][2], NEG2);

    // ---- exchange packed u-partials via smem aliased over xs
    __syncthreads();
    u64* part = (u64*)xs;   // 27 * 64 * 8 = 13824 B, fits
    #pragma unroll
    for (int o = 0; o < OCG; o++)
        part[(cg * OCG + o) * NPAIR + pp] = up[o];
    __syncthreads();

    // ---- threads tid < 192 finalize: o = tid/64, pair = tid&63
    if (tid < NPAIR * OCG) {
        int o   = tid >> 6;
        int fp  = tid & (NPAIR - 1);
        u64 g[9];
        #pragma unroll
        for (int gg = 0; gg < 9; gg++)
            g[gg] = part[(gg * OCG + o) * NPAIR + fp];
        u64 m0 = maj3s2(g[0], g[1], g[2], NEG2);
        u64 m1 = maj3s2(g[3], g[4], g[5], NEG2);
        u64 m2 = maj3s2(g[6], g[7], g[8], NEG2);
        u64 rr = maj3s2(m0, m1, m2, NEG2);
        u64 y2 = ffma2(pk2(2.0f, 2.0f), rr, pk2(-1.0f, -1.0f));
        float ylo, yhi;
        upk2(y2, ylo, yhi);

        int hg  = h0 + (fp >> 4);
        int wpx = 2 * (fp & 15);
        float2* op = (float2*)&out[(((size_t)n * NOC + (oc0 + o)) * HH + hg) * WW + wpx];
        *op = make_float2(ylo, yhi);
    }
}

extern "C" void kernel_launch(void* const* d_in, const int* in_sizes, int n_in,
                              void* d_out, int out_size) {
    const float* x = (const float*)d_in[0];     // (8,27,32,32) fp32
    const float* w = (const float*)d_in[1];     // (27,27,3,3) fp32
    float* out = (float*)d_out;                 // (8,27,32,32) fp32

    dim3 grid(8 * 8 * NCG);   // 576 blocks x 576 threads
    sconv_kernel<<<grid, NTHR>>>(x, w, out);
}

// round 11
// speedup vs baseline: 1.5392x; 1.5392x over previous
#include <cuda_runtime.h>

// SConv2d majority-gate conv, s-domain math, packed f32x2 (2 px/thread).
// R10: R9 design (prep kernels materialize padded+shifted x and packed
//      weights; main kernel staging-free, direct aligned LDG.64 windows)
//      with the prep_w grid bug fixed (26 blocks, covers all 6561 weights).

#define C_IN 27
#define NOC 27
#define HH 32
#define WW 32
#define PR 34                      // padded rows: h = -1..32
#define PW 36                      // padded cols
#define PCH (PR * PW)              // 1224 floats per (n,c)
#define XEL (8 * C_IN * PCH)       // 264384 elements per copy
#define OCG 3
#define WP2 10                     // packed-weight stride per (oc,c) in u64
#define NPAIR 64                   // pixel pairs per block (4 rows x 16)
#define NTHR (NPAIR * 3)           // 192
#define NWEL (NOC * C_IN * 9)      // 6561

typedef unsigned long long u64;

__device__ __align__(16) float g_xA[XEL];   // x[m] at col m+2 (halo -1)
__device__ __align__(16) float g_xB[XEL];   // x[m] at col m+3 (halo -1)
__device__ __align__(16) u64   g_wp[NOC * C_IN * WP2];

__device__ __forceinline__ u64 pk2(float lo, float hi) {
    u64 r; asm("mov.b64 %0,{%1,%2};" : "=l"(r) : "f"(lo), "f"(hi)); return r;
}
__device__ __forceinline__ void upk2(u64 v, float& lo, float& hi) {
    asm("mov.b64 {%0,%1},%2;" : "=f"(lo), "=f"(hi) : "l"(v));
}
__device__ __forceinline__ u64 ffma2(u64 a, u64 b, u64 c) {
    u64 d; asm("fma.rn.f32x2 %0,%1,%2,%3;" : "=l"(d) : "l"(a), "l"(b), "l"(c)); return d;
}
__device__ __forceinline__ u64 fmul2(u64 a, u64 b) {
    u64 d; asm("mul.rn.f32x2 %0,%1,%2;" : "=l"(d) : "l"(a), "l"(b)); return d;
}
__device__ __forceinline__ u64 fadd2(u64 a, u64 b) {
    u64 d; asm("add.rn.f32x2 %0,%1,%2;" : "=l"(d) : "l"(a), "l"(b)); return d;
}
__device__ __forceinline__ u64 maj3s2(u64 a, u64 b, u64 c, u64 NEG2) {
    u64 p = fmul2(a, b);
    u64 t = fadd2(a, b);
    u64 q = ffma2(NEG2, p, t);     // a+b-2ab
    return ffma2(q, c, p);         // ab + (a+b-2ab)c
}

// ---- prep: padded + shifted x copies --------------------------------------
__global__ __launch_bounds__(256) void prep_x_kernel(const float* __restrict__ x) {
    int e = blockIdx.x * 256 + threadIdx.x;
    if (e >= XEL) return;
    int col = e % PW;
    int r   = e / PW;
    int hp  = r % PR;          // padded row: gh = hp-1
    int nc  = r / PR;          // n*27 + c
    int gh  = hp - 1;
    const float* xb = x + (size_t)nc * (HH * WW);

    int mA = col - 2;
    float vA = -1.0f;
    if ((unsigned)gh < HH && (unsigned)mA < WW) vA = xb[gh * WW + mA];
    g_xA[e] = vA;

    int mB = col - 3;
    float vB = -1.0f;
    if ((unsigned)gh < HH && (unsigned)mB < WW) vB = xb[gh * WW + mB];
    g_xB[e] = vB;
}

// ---- prep: packed weights {w/2, w/2} --------------------------------------
__global__ __launch_bounds__(256) void prep_w_kernel(const float* __restrict__ w) {
    int e = blockIdx.x * 256 + threadIdx.x;
    if (e >= NWEL) return;
    int oc  = e / (C_IN * 9);
    int rem = e - oc * (C_IN * 9);
    int c = rem / 9;
    int k = rem - c * 9;
    float v = 0.5f * w[e];
    g_wp[(oc * C_IN + c) * WP2 + k] = pk2(v, v);
}

// ---- main ------------------------------------------------------------------
__global__ __launch_bounds__(NTHR, 4) void sconv_kernel(float* __restrict__ out) {
    __shared__ __align__(16) u64 part[3 * OCG * NPAIR];   // 9*64 u64 = 4608 B

    int b = blockIdx.x;
    int ocg  = b % 9;              // 0..8  -> oc group
    int tile = (b / 9) & 7;        // 0..7  -> 4-row tile
    int n    = b / 72;             // 0..7
    int h0 = tile * 4;
    int oc0 = ocg * OCG;

    int tid = threadIdx.x;
    int pp  = tid & (NPAIR - 1);   // 0..63
    int cg  = tid >> 6;            // 0..2 (9 channels each)
    int wc2 = pp & 15;
    int hl  = pp >> 4;             // 0..3
    int h   = h0 + hl;

    const u64 HALF2 = pk2(0.5f, 0.5f);
    const u64 NEG2  = pk2(-2.0f, -2.0f);

    int c0 = 9 * cg;
    size_t base = ((size_t)(n * C_IN + c0) * PR + h) * PW + 2 + 2 * wc2;
    const float* pA = g_xA + base;
    const float* pB = g_xB + base;

    u64 ub[OCG][3];
    u64 vtmp[OCG][3];

    #pragma unroll
    for (int g3 = 0; g3 < 3; g3++) {           // three 3-channel subgroups
        #pragma unroll
        for (int cl = 0; cl < 3; cl++) {
            int cc = g3 * 3 + cl;
            u64 xp[9];
            #pragma unroll
            for (int kh = 0; kh < 3; kh++) {
                size_t ro = (size_t)cc * PCH + kh * PW;
                xp[kh * 3 + 0] = __ldg((const u64*)(pB + ro));       // {x[w-1], x[w]}
                xp[kh * 3 + 1] = __ldg((const u64*)(pA + ro));       // {x[w],   x[w+1]}
                xp[kh * 3 + 2] = __ldg((const u64*)(pB + ro + 2));   // {x[w+1], x[w+2]}
            }
            int c = c0 + cc;
            #pragma unroll
            for (int o = 0; o < OCG; o++) {
                const u64* wb_ = &g_wp[((oc0 + o) * C_IN + c) * WP2];
                ulonglong2 q0 = __ldg((const ulonglong2*)wb_ + 0);
                ulonglong2 q1 = __ldg((const ulonglong2*)wb_ + 1);
                ulonglong2 q2 = __ldg((const ulonglong2*)wb_ + 2);
                ulonglong2 q3 = __ldg((const ulonglong2*)wb_ + 3);
                u64 w8 = __ldg(wb_ + 8);
                u64 wk[9] = {q0.x, q0.y, q1.x, q1.y, q2.x, q2.y, q3.x, q3.y, w8};
                u64 rkh[3];
                #pragma unroll
                for (int kh = 0; kh < 3; kh++) {
                    u64 s0 = ffma2(xp[kh * 3 + 0], wk[kh * 3 + 0], HALF2);
                    u64 s1 = ffma2(xp[kh * 3 + 1], wk[kh * 3 + 1], HALF2);
                    u64 s2 = ffma2(xp[kh * 3 + 2], wk[kh * 3 + 2], HALF2);
                    rkh[kh] = maj3s2(s0, s1, s2, NEG2);
                }
                vtmp[o][cl] = maj3s2(rkh[0], rkh[1], rkh[2], NEG2);
            }
        }
        #pragma unroll
        for (int o = 0; o < OCG; o++)
            ub[o][g3] = maj3s2(vtmp[o][0], vtmp[o][1], vtmp[o][2], NEG2);
    }

    // t-subtree root per oc for this cg
    u64 tp[OCG];
    #pragma unroll
    for (int o = 0; o < OCG; o++)
        tp[o] = maj3s2(ub[o][0], ub[o][1], ub[o][2], NEG2);

    // ---- exchange across the 3 cg groups
    #pragma unroll
    for (int o = 0; o < OCG; o++)
        part[(cg * OCG + o) * NPAIR + pp] = tp[o];
    __syncthreads();

    // thread (pp, cg) finalizes oc = cg
    u64 t0 = part[(0 * OCG + cg) * NPAIR + pp];
    u64 t1 = part[(1 * OCG + cg) * NPAIR + pp];
    u64 t2 = part[(2 * OCG + cg) * NPAIR + pp];
    u64 rr = maj3s2(t0, t1, t2, NEG2);
    u64 y2 = ffma2(pk2(2.0f, 2.0f), rr, pk2(-1.0f, -1.0f));
    float ylo, yhi;
    upk2(y2, ylo, yhi);

    float2* op = (float2*)&out[(((size_t)n * NOC + (oc0 + cg)) * HH + h) * WW + 2 * wc2];
    *op = make_float2(ylo, yhi);
}

extern "C" void kernel_launch(void* const* d_in, const int* in_sizes, int n_in,
                              void* d_out, int out_size) {
    const float* x = (const float*)d_in[0];     // (8,27,32,32) fp32
    const float* w = (const float*)d_in[1];     // (27,27,3,3) fp32
    float* out = (float*)d_out;                 // (8,27,32,32) fp32

    prep_x_kernel<<<(XEL + 255) / 256, 256>>>(x);
    prep_w_kernel<<<(NWEL + 255) / 256, 256>>>(w);
    sconv_kernel<<<8 * 8 * 9, NTHR>>>(out);     // 576 blocks x 192 threads
}

// round 12
// speedup vs baseline: 1.6051x; 1.0428x over previous
#include <cuda_runtime.h>

// SConv2d majority-gate conv, s-domain math, packed f32x2 (2 px/thread).
// R11: single fused prep kernel (vectorized padded+shifted x copies via
//      float4 stores + weight packing in extra blocks); main kernel
//      unchanged from R10 (staging-free, aligned LDG.64 windows, one wave).

#define C_IN 27
#define NOC 27
#define HH 32
#define WW 32
#define PR 34                      // padded rows: h = -1..32
#define PW 36                      // padded cols
#define PCH (PR * PW)              // 1224 floats per (n,c)
#define XEL (8 * C_IN * PCH)       // 264384 elements per copy
#define OCG 3
#define WP2 10                     // packed-weight stride per (oc,c) in u64
#define NPAIR 64                   // pixel pairs per block (4 rows x 16)
#define NTHR (NPAIR * 3)           // 192
#define NWEL (NOC * C_IN * 9)      // 6561

#define NROWS (8 * C_IN * PR)      // 7344 padded rows
#define NROWQ (NROWS * 9)          // 66096 quad tasks
#define XBLK ((NROWQ + 255) / 256) // 259
#define WBLK ((NWEL + 255) / 256)  // 26

typedef unsigned long long u64;

__device__ __align__(16) float g_xA[XEL];   // x[m] at col m+2 (halo -1)
__device__ __align__(16) float g_xB[XEL];   // x[m] at col m+3 (halo -1)
__device__ __align__(16) u64   g_wp[NOC * C_IN * WP2];

__device__ __forceinline__ u64 pk2(float lo, float hi) {
    u64 r; asm("mov.b64 %0,{%1,%2};" : "=l"(r) : "f"(lo), "f"(hi)); return r;
}
__device__ __forceinline__ void upk2(u64 v, float& lo, float& hi) {
    asm("mov.b64 {%0,%1},%2;" : "=f"(lo), "=f"(hi) : "l"(v));
}
__device__ __forceinline__ u64 ffma2(u64 a, u64 b, u64 c) {
    u64 d; asm("fma.rn.f32x2 %0,%1,%2,%3;" : "=l"(d) : "l"(a), "l"(b), "l"(c)); return d;
}
__device__ __forceinline__ u64 fmul2(u64 a, u64 b) {
    u64 d; asm("mul.rn.f32x2 %0,%1,%2;" : "=l"(d) : "l"(a), "l"(b)); return d;
}
__device__ __forceinline__ u64 fadd2(u64 a, u64 b) {
    u64 d; asm("add.rn.f32x2 %0,%1,%2;" : "=l"(d) : "l"(a), "l"(b)); return d;
}
__device__ __forceinline__ u64 maj3s2(u64 a, u64 b, u64 c, u64 NEG2) {
    u64 p = fmul2(a, b);
    u64 t = fadd2(a, b);
    u64 q = ffma2(NEG2, p, t);     // a+b-2ab
    return ffma2(q, c, p);         // ab + (a+b-2ab)c
}

// ---- fused prep: padded+shifted x copies (float4 stores) + packed weights --
__global__ __launch_bounds__(256) void prep_kernel(const float* __restrict__ x,
                                                   const float* __restrict__ w) {
    int bid = blockIdx.x;
    if (bid < XBLK) {
        int t = bid * 256 + threadIdx.x;
        if (t >= NROWQ) return;
        int r = t / 9;                 // padded row id
        int q = t - r * 9;             // quad 0..8 (cols 4q..4q+3)
        int hp = r % PR;
        int nc = r / PR;               // n*27 + c
        int gh = hp - 1;
        bool rowok = (unsigned)gh < (unsigned)HH;
        const float* xb = x + (size_t)nc * (HH * WW) + gh * WW;

        // 5 source values covering m = 4q-3 .. 4q+1 (serves both copies)
        float v[5];
        int m0 = 4 * q - 3;
        #pragma unroll
        for (int j = 0; j < 5; j++) {
            int m = m0 + j;
            v[j] = (rowok && (unsigned)m < (unsigned)WW) ? xb[m] : -1.0f;
        }
        int base = r * PW + 4 * q;     // 16B-aligned (36 = 4*9)
        *(float4*)&g_xA[base] = make_float4(v[1], v[2], v[3], v[4]);  // m = col-2
        *(float4*)&g_xB[base] = make_float4(v[0], v[1], v[2], v[3]);  // m = col-3
    } else {
        int e = (bid - XBLK) * 256 + threadIdx.x;
        if (e >= NWEL) return;
        int oc  = e / (C_IN * 9);
        int rem = e - oc * (C_IN * 9);
        int c = rem / 9;
        int k = rem - c * 9;
        float v = 0.5f * w[e];
        g_wp[(oc * C_IN + c) * WP2 + k] = pk2(v, v);
    }
}

// ---- main ------------------------------------------------------------------
__global__ __launch_bounds__(NTHR, 4) void sconv_kernel(float* __restrict__ out) {
    __shared__ __align__(16) u64 part[3 * OCG * NPAIR];   // 9*64 u64 = 4608 B

    int b = blockIdx.x;
    int ocg  = b % 9;              // 0..8  -> oc group
    int tile = (b / 9) & 7;        // 0..7  -> 4-row tile
    int n    = b / 72;             // 0..7
    int h0 = tile * 4;
    int oc0 = ocg * OCG;

    int tid = threadIdx.x;
    int pp  = tid & (NPAIR - 1);   // 0..63
    int cg  = tid >> 6;            // 0..2 (9 channels each)
    int wc2 = pp & 15;
    int hl  = pp >> 4;             // 0..3
    int h   = h0 + hl;

    const u64 HALF2 = pk2(0.5f, 0.5f);
    const u64 NEG2  = pk2(-2.0f, -2.0f);

    int c0 = 9 * cg;
    size_t base = ((size_t)(n * C_IN + c0) * PR + h) * PW + 2 + 2 * wc2;
    const float* pA = g_xA + base;
    const float* pB = g_xB + base;

    u64 ub[OCG][3];
    u64 vtmp[OCG][3];

    #pragma unroll
    for (int g3 = 0; g3 < 3; g3++) {           // three 3-channel subgroups
        #pragma unroll
        for (int cl = 0; cl < 3; cl++) {
            int cc = g3 * 3 + cl;
            u64 xp[9];
            #pragma unroll
            for (int kh = 0; kh < 3; kh++) {
                size_t ro = (size_t)cc * PCH + kh * PW;
                xp[kh * 3 + 0] = __ldg((const u64*)(pB + ro));       // {x[w-1], x[w]}
                xp[kh * 3 + 1] = __ldg((const u64*)(pA + ro));       // {x[w],   x[w+1]}
                xp[kh * 3 + 2] = __ldg((const u64*)(pB + ro + 2));   // {x[w+1], x[w+2]}
            }
            int c = c0 + cc;
            #pragma unroll
            for (int o = 0; o < OCG; o++) {
                const u64* wb_ = &g_wp[((oc0 + o) * C_IN + c) * WP2];
                ulonglong2 q0 = __ldg((const ulonglong2*)wb_ + 0);
                ulonglong2 q1 = __ldg((const ulonglong2*)wb_ + 1);
                ulonglong2 q2 = __ldg((const ulonglong2*)wb_ + 2);
                ulonglong2 q3 = __ldg((const ulonglong2*)wb_ + 3);
                u64 w8 = __ldg(wb_ + 8);
                u64 wk[9] = {q0.x, q0.y, q1.x, q1.y, q2.x, q2.y, q3.x, q3.y, w8};
                u64 rkh[3];
                #pragma unroll
                for (int kh = 0; kh < 3; kh++) {
                    u64 s0 = ffma2(xp[kh * 3 + 0], wk[kh * 3 + 0], HALF2);
                    u64 s1 = ffma2(xp[kh * 3 + 1], wk[kh * 3 + 1], HALF2);
                    u64 s2 = ffma2(xp[kh * 3 + 2], wk[kh * 3 + 2], HALF2);
                    rkh[kh] = maj3s2(s0, s1, s2, NEG2);
                }
                vtmp[o][cl] = maj3s2(rkh[0], rkh[1], rkh[2], NEG2);
            }
        }
        #pragma unroll
        for (int o = 0; o < OCG; o++)
            ub[o][g3] = maj3s2(vtmp[o][0], vtmp[o][1], vtmp[o][2], NEG2);
    }

    // t-subtree root per oc for this cg
    u64 tp[OCG];
    #pragma unroll
    for (int o = 0; o < OCG; o++)
        tp[o] = maj3s2(ub[o][0], ub[o][1], ub[o][2], NEG2);

    // ---- exchange across the 3 cg groups
    #pragma unroll
    for (int o = 0; o < OCG; o++)
        part[(cg * OCG + o) * NPAIR + pp] = tp[o];
    __syncthreads();

    // thread (pp, cg) finalizes oc = cg
    u64 t0 = part[(0 * OCG + cg) * NPAIR + pp];
    u64 t1 = part[(1 * OCG + cg) * NPAIR + pp];
    u64 t2 = part[(2 * OCG + cg) * NPAIR + pp];
    u64 rr = maj3s2(t0, t1, t2, NEG2);
    u64 y2 = ffma2(pk2(2.0f, 2.0f), rr, pk2(-1.0f, -1.0f));
    float ylo, yhi;
    upk2(y2, ylo, yhi);

    float2* op = (float2*)&out[(((size_t)n * NOC + (oc0 + cg)) * HH + h) * WW + 2 * wc2];
    *op = make_float2(ylo, yhi);
}

extern "C" void kernel_launch(void* const* d_in, const int* in_sizes, int n_in,
                              void* d_out, int out_size) {
    const float* x = (const float*)d_in[0];     // (8,27,32,32) fp32
    const float* w = (const float*)d_in[1];     // (27,27,3,3) fp32
    float* out = (float*)d_out;                 // (8,27,32,32) fp32

    prep_kernel<<<XBLK + WBLK, 256>>>(x, w);    // 285 blocks
    sconv_kernel<<<8 * 8 * 9, NTHR>>>(out);     // 576 blocks x 192 threads
}